// round 1
// baseline (speedup 1.0000x reference)
#include <cuda_runtime.h>
#include <math.h>

#define BB  64
#define LCC 512
#define LQQ 64
#define DD  256

// Scratch (device globals; no allocation allowed)
__device__ float g_Qp[(size_t)BB * LQQ * DD];          // wi*q + wc          (4 MB)
__device__ float g_t[BB * LQQ];                        // <q,wq> + bias
__device__ float g_S1[(size_t)BB * LCC * LQQ];         // row-softmax(S)     (8 MB)
__device__ float g_St[(size_t)BB * LQQ * LCC];         // S^T, then col-softmax in place (8 MB)
__device__ float g_C2[(size_t)BB * LQQ * DD];          // S2^T @ contex      (4 MB)

// ---------------------------------------------------------------------------
// K0: Q'[b,j,d] = wi[d]*q[b,j,d] + wc[d];  t[b,j] = <q[b,j], wq> + bias
// grid = B*LQ blocks, 256 threads (one per d)
// ---------------------------------------------------------------------------
__global__ void k0_prep(const float* __restrict__ q,
                        const float* __restrict__ W,
                        const float* __restrict__ bias) {
    const int bj = blockIdx.x;
    const int d  = threadIdx.x;
    const float qv = q[(size_t)bj * DD + d];
    const float wq = W[d];
    const float wc = W[DD + d];
    const float wi = W[2 * DD + d];
    g_Qp[(size_t)bj * DD + d] = fmaf(wi, qv, wc);

    float v = qv * wq;
    #pragma unroll
    for (int o = 16; o > 0; o >>= 1) v += __shfl_xor_sync(0xffffffffu, v, o);
    __shared__ float red[8];
    if ((threadIdx.x & 31) == 0) red[threadIdx.x >> 5] = v;
    __syncthreads();
    if (threadIdx.x == 0) {
        float s = 0.f;
        #pragma unroll
        for (int i = 0; i < 8; i++) s += red[i];
        g_t[bj] = s + bias[0];
    }
}

// ---------------------------------------------------------------------------
// K1: S = contex @ Q'^T + t  (per batch: 512x64, K=256), fused row softmax.
// Writes S1[b,i,j] (softmax over j) and raw S^T into g_St[b,j,i].
// grid = (LC/64, B), 256 threads, 64x64 tile, 4x4 per thread.
// ---------------------------------------------------------------------------
__global__ void k1_score(const float* __restrict__ contex) {
    const int b  = blockIdx.y;
    const int i0 = blockIdx.x * 64;
    const int tid = threadIdx.x;
    const int tx = tid & 15, ty = tid >> 4;

    __shared__ float As[16][68];   // As[k][m] = contex[i0+m][k0+k]
    __shared__ float Bs[16][68];   // Bs[k][j] = Q'[j][k0+k]
    __shared__ float ts[64];
    if (tid < 64) ts[tid] = g_t[b * LQQ + tid];

    const float* Cb = contex + (size_t)b * LCC * DD;
    const float* Qp = g_Qp  + (size_t)b * LQQ * DD;

    float acc[4][4];
    #pragma unroll
    for (int a = 0; a < 4; a++)
        #pragma unroll
        for (int c = 0; c < 4; c++) acc[a][c] = 0.f;

    const int lr = tid >> 2;          // 0..63
    const int lc = (tid & 3) * 4;     // 0,4,8,12

    for (int k0 = 0; k0 < DD; k0 += 16) {
        float4 va = *(const float4*)&Cb[(size_t)(i0 + lr) * DD + k0 + lc];
        float4 vb = *(const float4*)&Qp[(size_t)lr * DD + k0 + lc];
        As[lc + 0][lr] = va.x; As[lc + 1][lr] = va.y; As[lc + 2][lr] = va.z; As[lc + 3][lr] = va.w;
        Bs[lc + 0][lr] = vb.x; Bs[lc + 1][lr] = vb.y; Bs[lc + 2][lr] = vb.z; Bs[lc + 3][lr] = vb.w;
        __syncthreads();
        #pragma unroll
        for (int k = 0; k < 16; k++) {
            float4 a4 = *(const float4*)&As[k][ty * 4];
            float4 b4 = *(const float4*)&Bs[k][tx * 4];
            float av[4] = {a4.x, a4.y, a4.z, a4.w};
            float bv[4] = {b4.x, b4.y, b4.z, b4.w};
            #pragma unroll
            for (int a = 0; a < 4; a++)
                #pragma unroll
                for (int c = 0; c < 4; c++)
                    acc[a][c] = fmaf(av[a], bv[c], acc[a][c]);
        }
        __syncthreads();
    }

    // add t[j]; write raw S^T (needed for column softmax)
    #pragma unroll
    for (int a = 0; a < 4; a++) {
        const int i = i0 + ty * 4 + a;
        #pragma unroll
        for (int c = 0; c < 4; c++) {
            const int j = tx * 4 + c;
            acc[a][c] += ts[j];
            g_St[((size_t)b * LQQ + j) * LCC + i] = acc[a][c];
        }
    }

    // row softmax over j (full 64 cols live in this block; 16 lanes share a row)
    #pragma unroll
    for (int a = 0; a < 4; a++) {
        float m = fmaxf(fmaxf(acc[a][0], acc[a][1]), fmaxf(acc[a][2], acc[a][3]));
        #pragma unroll
        for (int o = 1; o < 16; o <<= 1) m = fmaxf(m, __shfl_xor_sync(0xffffffffu, m, o));
        float e0 = expf(acc[a][0] - m), e1 = expf(acc[a][1] - m);
        float e2 = expf(acc[a][2] - m), e3 = expf(acc[a][3] - m);
        float s = e0 + e1 + e2 + e3;
        #pragma unroll
        for (int o = 1; o < 16; o <<= 1) s += __shfl_xor_sync(0xffffffffu, s, o);
        const float inv = 1.f / s;
        const int i = i0 + ty * 4 + a;
        float4 o4 = make_float4(e0 * inv, e1 * inv, e2 * inv, e3 * inv);
        *(float4*)&g_S1[((size_t)b * LCC + i) * LQQ + tx * 4] = o4;
    }
}

// ---------------------------------------------------------------------------
// K2: column softmax (over i, length 512) applied in place on g_St rows.
// grid = B*LQ blocks of 256 threads (2 elements per thread).
// ---------------------------------------------------------------------------
__global__ void k2_colsm() {
    const int bj = blockIdx.x;
    float* row = g_St + (size_t)bj * LCC;
    const int tid = threadIdx.x;
    float v0 = row[tid], v1 = row[tid + 256];

    __shared__ float red[8];
    float m = fmaxf(v0, v1);
    #pragma unroll
    for (int o = 16; o > 0; o >>= 1) m = fmaxf(m, __shfl_xor_sync(0xffffffffu, m, o));
    if ((tid & 31) == 0) red[tid >> 5] = m;
    __syncthreads();
    m = fmaxf(fmaxf(fmaxf(red[0], red[1]), fmaxf(red[2], red[3])),
              fmaxf(fmaxf(red[4], red[5]), fmaxf(red[6], red[7])));
    __syncthreads();

    float e0 = expf(v0 - m), e1 = expf(v1 - m);
    float s = e0 + e1;
    #pragma unroll
    for (int o = 16; o > 0; o >>= 1) s += __shfl_xor_sync(0xffffffffu, s, o);
    if ((tid & 31) == 0) red[tid >> 5] = s;
    __syncthreads();
    s = red[0] + red[1] + red[2] + red[3] + red[4] + red[5] + red[6] + red[7];
    const float inv = 1.f / s;
    row[tid]       = e0 * inv;
    row[tid + 256] = e1 * inv;
}

// ---------------------------------------------------------------------------
// K3: C2 = S2^T @ contex  (per batch: 64x512 @ 512x256 -> 64x256)
// grid = (D/64, B), 64x64 tile, K-chunks of 16.
// ---------------------------------------------------------------------------
__global__ void k3_c2(const float* __restrict__ contex) {
    const int b  = blockIdx.y;
    const int n0 = blockIdx.x * 64;
    const int tid = threadIdx.x;
    const int tx = tid & 15, ty = tid >> 4;

    __shared__ float As[16][68];   // As[k][j] = S2t[j][k0+k]
    __shared__ float Bs[16][68];   // Bs[k][n] = contex[k0+k][n0+n]

    const float* S2t = g_St + (size_t)b * LQQ * LCC;
    const float* Cb  = contex + (size_t)b * LCC * DD;

    float acc[4][4];
    #pragma unroll
    for (int a = 0; a < 4; a++)
        #pragma unroll
        for (int c = 0; c < 4; c++) acc[a][c] = 0.f;

    const int lr = tid >> 2;         // A: row j 0..63
    const int lc = (tid & 3) * 4;    // A: k offset
    const int br = tid >> 4;         // B: row k 0..15
    const int bc = (tid & 15) * 4;   // B: col offset

    for (int k0 = 0; k0 < LCC; k0 += 16) {
        float4 va = *(const float4*)&S2t[(size_t)lr * LCC + k0 + lc];
        As[lc + 0][lr] = va.x; As[lc + 1][lr] = va.y; As[lc + 2][lr] = va.z; As[lc + 3][lr] = va.w;
        *(float4*)&Bs[br][bc] = *(const float4*)&Cb[(size_t)(k0 + br) * DD + n0 + bc];
        __syncthreads();
        #pragma unroll
        for (int k = 0; k < 16; k++) {
            float4 a4 = *(const float4*)&As[k][ty * 4];
            float4 b4 = *(const float4*)&Bs[k][tx * 4];
            float av[4] = {a4.x, a4.y, a4.z, a4.w};
            float bv[4] = {b4.x, b4.y, b4.z, b4.w};
            #pragma unroll
            for (int a = 0; a < 4; a++)
                #pragma unroll
                for (int c = 0; c < 4; c++)
                    acc[a][c] = fmaf(av[a], bv[c], acc[a][c]);
        }
        __syncthreads();
    }
    #pragma unroll
    for (int a = 0; a < 4; a++) {
        const int j = ty * 4 + a;
        float4 o4 = make_float4(acc[a][0], acc[a][1], acc[a][2], acc[a][3]);
        *(float4*)&g_C2[((size_t)b * LQQ + j) * DD + n0 + tx * 4] = o4;
    }
}

// ---------------------------------------------------------------------------
// K4: A = S1 @ question, Bm = S1 @ C2 (K=64), fused output assembly:
// out[b,i] = [contex | A | contex*A | contex*Bm]
// grid = (LC/64, B). S1 tile resident in smem; 8 N-chunks of 64.
// ---------------------------------------------------------------------------
__global__ void k4_out(const float* __restrict__ contex,
                       const float* __restrict__ question,
                       float* __restrict__ out) {
    const int b  = blockIdx.y;
    const int i0 = blockIdx.x * 64;
    const int tid = threadIdx.x;
    const int tx = tid & 15, ty = tid >> 4;

    __shared__ float As[64][68];   // As[k=j][i] = S1[i0+i][j]
    __shared__ float Bs[64][68];   // B tile, reused for contex tile in epilogue

    const float* S1b = g_S1 + (size_t)b * LCC * LQQ;
    {
        const int j4 = (tid & 15) * 4;
        #pragma unroll
        for (int r0 = 0; r0 < 64; r0 += 16) {
            const int i = r0 + (tid >> 4);
            float4 v = *(const float4*)&S1b[(size_t)(i0 + i) * LQQ + j4];
            As[j4 + 0][i] = v.x; As[j4 + 1][i] = v.y; As[j4 + 2][i] = v.z; As[j4 + 3][i] = v.w;
        }
    }

    const float* Cb  = contex   + (size_t)b * LCC * DD;
    const float* Qb  = question + (size_t)b * LQQ * DD;
    const float* C2b = g_C2     + (size_t)b * LQQ * DD;
    float* outb = out + (size_t)b * LCC * 1024;

    for (int chunk = 0; chunk < 8; chunk++) {
        const float* Bsrc = (chunk < 4) ? (Qb + chunk * 64) : (C2b + (chunk - 4) * 64);
        __syncthreads();   // As ready (first iter) / Bs safe to overwrite (later iters)
        #pragma unroll
        for (int p = 0; p < 4; p++) {
            const int idx = tid + p * 256;
            const int r  = idx >> 4;
            const int c4 = (idx & 15) * 4;
            *(float4*)&Bs[r][c4] = *(const float4*)&Bsrc[(size_t)r * DD + c4];
        }
        __syncthreads();

        float acc[4][4];
        #pragma unroll
        for (int a = 0; a < 4; a++)
            #pragma unroll
            for (int c = 0; c < 4; c++) acc[a][c] = 0.f;

        #pragma unroll 8
        for (int k = 0; k < 64; k++) {
            float4 a4 = *(const float4*)&As[k][ty * 4];
            float4 b4 = *(const float4*)&Bs[k][tx * 4];
            float av[4] = {a4.x, a4.y, a4.z, a4.w};
            float bv[4] = {b4.x, b4.y, b4.z, b4.w};
            #pragma unroll
            for (int a = 0; a < 4; a++)
                #pragma unroll
                for (int c = 0; c < 4; c++)
                    acc[a][c] = fmaf(av[a], bv[c], acc[a][c]);
        }
        __syncthreads();

        // load contex tile into Bs for epilogue
        const int cc0 = ((chunk < 4) ? chunk : (chunk - 4)) * 64;
        #pragma unroll
        for (int p = 0; p < 4; p++) {
            const int idx = tid + p * 256;
            const int r  = idx >> 4;
            const int c4 = (idx & 15) * 4;
            *(float4*)&Bs[r][c4] = *(const float4*)&Cb[(size_t)(i0 + r) * DD + cc0 + c4];
        }
        __syncthreads();

        #pragma unroll
        for (int a = 0; a < 4; a++) {
            const int i = i0 + ty * 4 + a;
            float4 c4   = *(const float4*)&Bs[ty * 4 + a][tx * 4];
            float4 acc4 = make_float4(acc[a][0], acc[a][1], acc[a][2], acc[a][3]);
            float4 prod = make_float4(c4.x * acc4.x, c4.y * acc4.y,
                                      c4.z * acc4.z, c4.w * acc4.w);
            float* orow = outb + (size_t)i * 1024;
            if (chunk < 4) {
                const int col = chunk * 64 + tx * 4;
                *(float4*)&orow[col]        = c4;     // contex passthrough
                *(float4*)&orow[256 + col]  = acc4;   // A
                *(float4*)&orow[512 + col]  = prod;   // contex * A
            } else {
                const int col = (chunk - 4) * 64 + tx * 4;
                *(float4*)&orow[768 + col]  = prod;   // contex * Bm
            }
        }
    }
}

// ---------------------------------------------------------------------------
extern "C" void kernel_launch(void* const* d_in, const int* in_sizes, int n_in,
                              void* d_out, int out_size) {
    const float* contex   = (const float*)d_in[0];
    const float* question = (const float*)d_in[1];
    const float* W        = (const float*)d_in[2];
    const float* bias     = (const float*)d_in[3];
    float* out = (float*)d_out;

    k0_prep<<<BB * LQQ, 256>>>(question, W, bias);
    k1_score<<<dim3(LCC / 64, BB), 256>>>(contex);
    k2_colsm<<<BB * LQQ, 256>>>();
    k3_c2<<<dim3(DD / 64, BB), 256>>>(contex);
    k4_out<<<dim3(LCC / 64, BB), 256>>>(contex, question, out);
}